// round 1
// baseline (speedup 1.0000x reference)
#include <cuda_runtime.h>
#include <cstdint>

// ---------------------------------------------------------------------------
// DynamicPointConvBackBone: only the 8192 resampled rows are observable, so we
// compute gather + [rows,1728]x[1728,128] GEMM + LayerNorm + ReLU only for them.
// GEMM uses packed fma.rn.f32x2 (2 fp32 FMA per FMA-pipe slot on sm_103a).
// ---------------------------------------------------------------------------

__device__ int g_idx_is64;

// Detect whether voxel_idx was serialized as int64 or int32.
// int32 data read as int64 pairs -> |v| >= 2^32 almost surely; int64 data -> v in [-N, N).
__global__ void detect_idx_dtype(const void* __restrict__ vidx, int nelem, int N) {
    const long long* p = (const long long*)vidx;
    int cnt = (nelem >= 16) ? 8 : (nelem / 2);
    int ok = (cnt > 0) ? 1 : 0;
    for (int i = 0; i < cnt; ++i) {
        long long v = p[i];
        if (v < -(long long)N || v >= (long long)N) ok = 0;
    }
    g_idx_is64 = ok;
}

static __device__ __forceinline__ unsigned smaddr(const void* p) {
    return (unsigned)__cvta_generic_to_shared(p);
}

#define FMA2(acc, a, b) \
    asm("fma.rn.f32x2 %0, %1, %2, %3;" : "=l"(acc) : "l"(a), "l"(b), "l"(acc))

// SMEM layout (dynamic):
//  [0, 2048)  u64 : g2  duplicated gathered features, g2[r*64 + kk] = (g,g)   (16 KB)
//  [2048, 6272) u64 : w2 column-pair W, w2[cp*66 + kk] = (W[k][2cp], W[k][2cp+1]) (33 KB)
//  tail: int src[32], int valid[32]
#define G2_U64   2048
#define W2_U64   4224
#define W2S      66

__global__ __launch_bounds__(128, 1)
void dpc_main_kernel(const float* __restrict__ features,
                     const void*  __restrict__ vidx,
                     const int*   __restrict__ num_list,
                     const float* __restrict__ Wm,
                     const float* __restrict__ gamma,
                     const float* __restrict__ beta,
                     float* __restrict__ out_feat,
                     int N, int M, int K3, int B, int K, int R)
{
    extern __shared__ unsigned long long smem[];
    unsigned long long* g2sh = smem;
    unsigned long long* w2sh = smem + G2_U64;
    int* srcsh   = (int*)(smem + G2_U64 + W2_U64);
    int* validsh = srcsh + 32;

    const int tid  = threadIdx.x;
    const int wid  = tid >> 5;
    const int lane = tid & 31;
    const int cp   = tid & 63;   // column pair 0..63 (cols 2cp, 2cp+1)
    const int rg   = tid >> 6;   // row group 0/1 (rows rg*16 .. rg*16+15)
    const int row0 = blockIdx.x * 32;
    const int is64 = g_idx_is64;

    // --- per-block source rows + validity ---
    if (tid < 32) {
        int grow = row0 + tid;
        int src = 0, valid = 0;
        if (grow < R) {
            int b = grow / K;
            int j = grow - b * K;
            int off = 0;
            for (int t = 0; t < b; ++t) off += num_list[t];
            int end = min(num_list[b], K);
            valid = (j < end) ? 1 : 0;
            int s = off + j;
            s = max(0, min(s, M - 1));
            src = s;
        }
        srcsh[tid]   = src;
        validsh[tid] = valid;
    }

    unsigned long long acc[16];
#pragma unroll
    for (int r = 0; r < 16; ++r) acc[r] = 0ull;

    const long long* vidx64 = (const long long*)vidx;
    const int*       vidx32 = (const int*)vidx;

    __syncthreads();

    const int wkk  = tid >> 6;   // 0/1: parity class of W kk rows this thread loads
    const int wcp  = tid & 63;

    for (int n = 0; n < K3; ++n) {
        if (n) __syncthreads();   // previous compute must finish before overwrite

        // ---- stage W chunk: rows k = n*64 + kk, as column-pair u64 [cp][kk] ----
        {
            const float* Wb = Wm + (size_t)(n * 64) * 128 + 2 * wcp;
#pragma unroll
            for (int i = 0; i < 32; ++i) {
                int kk = wkk + i * 2;
                float2 wv = *(const float2*)(Wb + (size_t)kk * 128);
                union { unsigned long long u; float2 f; } pk;
                pk.f = wv;
                w2sh[wcp * W2S + kk] = pk.u;
            }
        }

        // ---- stage gathered features, duplicated (g,g): warp w -> rows w*8..w*8+7 ----
        {
#pragma unroll
            for (int rr = 0; rr < 8; ++rr) {
                int r = wid * 8 + rr;
                int src = srcsh[r];
                long long idx = is64 ? vidx64[(size_t)src * K3 + n]
                                     : (long long)vidx32[src * K3 + n];
                float2 v = make_float2(0.f, 0.f);
                if (idx >= 0) {
                    long long ii = (idx < (long long)(N - 1)) ? idx : (long long)(N - 1);
                    v = *(const float2*)(features + ii * 64 + lane * 2);
                }
                unsigned vx = __float_as_uint(v.x);
                unsigned vy = __float_as_uint(v.y);
                unsigned a = smaddr(&g2sh[r * 64 + lane * 2]);
                asm volatile("st.shared.v4.b32 [%0], {%1,%1,%2,%2};"
                             :: "r"(a), "r"(vx), "r"(vy));
            }
        }
        __syncthreads();

        // ---- compute: 17 LDS.128 + 32 FFMA2 per kk-pair ----
        const unsigned gbase = smaddr(&g2sh[(rg * 16) * 64]);
        const unsigned wbase = smaddr(&w2sh[cp * W2S]);
#pragma unroll 4
        for (int kk2 = 0; kk2 < 64; kk2 += 2) {
            unsigned long long wA, wB;
            asm("ld.shared.v2.b64 {%0,%1}, [%2];"
                : "=l"(wA), "=l"(wB) : "r"(wbase + kk2 * 8));
#pragma unroll
            for (int r = 0; r < 16; ++r) {
                unsigned long long gA, gB;
                asm("ld.shared.v2.b64 {%0,%1}, [%2];"
                    : "=l"(gA), "=l"(gB) : "r"(gbase + (r * 64 + kk2) * 8));
                FMA2(acc[r], gA, wA);
                FMA2(acc[r], gB, wB);
            }
        }
    }

    // ---- epilogue: stage 32x128 tile, LayerNorm + ReLU, store ----
    __syncthreads();
    float* outb = (float*)g2sh;   // reuse g2 region: 32*128*4 = 16 KB
#pragma unroll
    for (int r = 0; r < 16; ++r) {
        int row = rg * 16 + r;
        unsigned lo, hi;
        asm("mov.b64 {%0,%1}, %2;" : "=r"(lo), "=r"(hi) : "l"(acc[r]));
        unsigned a = smaddr(&outb[row * 128 + 2 * cp]);
        asm volatile("st.shared.v2.b32 [%0], {%1,%2};" :: "r"(a), "r"(lo), "r"(hi));
    }
    __syncthreads();

    float4 gmv = *(const float4*)(gamma + lane * 4);
    float4 btv = *(const float4*)(beta + lane * 4);

#pragma unroll
    for (int rr = 0; rr < 8; ++rr) {
        int row  = wid * 8 + rr;
        int grow = row0 + row;
        if (grow >= R) continue;
        float4 x = *(const float4*)(&outb[row * 128 + lane * 4]);
        float s  = x.x + x.y + x.z + x.w;
        float sq = x.x * x.x + x.y * x.y + x.z * x.z + x.w * x.w;
#pragma unroll
        for (int o = 16; o; o >>= 1) {
            s  += __shfl_xor_sync(0xffffffffu, s,  o);
            sq += __shfl_xor_sync(0xffffffffu, sq, o);
        }
        float mu   = s * (1.f / 128.f);
        float var  = sq * (1.f / 128.f) - mu * mu;
        float rstd = rsqrtf(var + 1e-3f);
        float4 y;
        if (validsh[row]) {
            y.x = fmaxf((x.x - mu) * rstd * gmv.x + btv.x, 0.f);
            y.y = fmaxf((x.y - mu) * rstd * gmv.y + btv.y, 0.f);
            y.z = fmaxf((x.z - mu) * rstd * gmv.z + btv.z, 0.f);
            y.w = fmaxf((x.w - mu) * rstd * gmv.w + btv.w, 0.f);
        } else {
            y = make_float4(0.f, 0.f, 0.f, 0.f);
        }
        *(float4*)(out_feat + (size_t)grow * 128 + lane * 4) = y;
    }
}

__global__ void dpc_coords_kernel(const float* __restrict__ center,
                                  const int* __restrict__ num_list,
                                  float* __restrict__ out_coor,
                                  int B, int K, int M, int R)
{
    int i = blockIdx.x * blockDim.x + threadIdx.x;
    if (i >= R) return;
    int b = i / K;
    int j = i - b * K;
    int off = 0;
    for (int t = 0; t < b; ++t) off += num_list[t];
    int end   = min(num_list[b], K);
    int valid = (j < end) ? 1 : 0;
    int s = off + j;
    s = max(0, min(s, M - 1));
    float x = 0.f, y = 0.f, z = 0.f;
    if (valid) {
        x = center[s * 3 + 0];
        y = center[s * 3 + 1];
        z = center[s * 3 + 2];
    }
    float c0 = (b < B - 1) ? (float)(b + 1) : 0.f;
    float4 o = make_float4(c0, x, y, z);
    *(float4*)(out_coor + (size_t)i * 4) = o;
}

extern "C" void kernel_launch(void* const* d_in, const int* in_sizes, int n_in,
                              void* d_out, int out_size) {
    const float* features = (const float*)d_in[0];
    const float* center   = (const float*)d_in[1];
    const void*  vidx     = d_in[2];
    const int*   num_list = (const int*)d_in[3];
    const float* Wm       = (const float*)d_in[4];
    const float* gamma    = (const float*)d_in[5];
    const float* beta     = (const float*)d_in[6];

    int C_OUT = in_sizes[5];                       // 128
    int M     = in_sizes[1] / 3;                   // 40000
    int K3    = in_sizes[2] / M;                   // 27
    int C_IN  = in_sizes[4] / (C_OUT * K3);        // 64
    int N     = in_sizes[0] / C_IN;                // 200000
    int B     = in_sizes[3];                       // 4
    int K     = out_size / (B * (C_OUT + 4));      // 2048
    int R     = B * K;                             // 8192

    float* out_feat = (float*)d_out;
    float* out_coor = out_feat + (size_t)R * C_OUT;

    detect_idx_dtype<<<1, 1>>>(vidx, in_sizes[2], N);

    int smem_bytes = (G2_U64 + W2_U64) * 8 + 64 * (int)sizeof(int);
    cudaFuncSetAttribute(dpc_main_kernel,
                         cudaFuncAttributeMaxDynamicSharedMemorySize, smem_bytes);
    dpc_main_kernel<<<(R + 31) / 32, 128, smem_bytes>>>(
        features, vidx, num_list, Wm, gamma, beta, out_feat,
        N, M, K3, B, K, R);

    dpc_coords_kernel<<<(R + 255) / 256, 256>>>(center, num_list, out_coor, B, K, M, R);
}

// round 2
// speedup vs baseline: 1.4701x; 1.4701x over previous
#include <cuda_runtime.h>
#include <cstdint>

// ---------------------------------------------------------------------------
// DynamicPointConvBackBone: only the 8192 resampled rows are observable.
// Register-blocked SGEMM (32x128 block tile, 8x4 thread tile) with packed
// fma.rn.f32x2. A (gathered features) staged duplicated (a,a) in SMEM and read
// via warp-broadcast; B (= W chunk) staged as a straight contiguous copy.
// ---------------------------------------------------------------------------

__device__ int g_idx_is64;

// Detect whether voxel_idx was serialized as int64 or int32.
__global__ void detect_idx_dtype(const void* __restrict__ vidx, int nelem, int N) {
    const long long* p = (const long long*)vidx;
    int cnt = (nelem >= 16) ? 8 : (nelem / 2);
    int ok = (cnt > 0) ? 1 : 0;
    for (int i = 0; i < cnt; ++i) {
        long long v = p[i];
        if (v < -(long long)N || v >= (long long)N) ok = 0;
    }
    g_idx_is64 = ok;
}

static __device__ __forceinline__ unsigned smaddr(const void* p) {
    return (unsigned)__cvta_generic_to_shared(p);
}

#define FMA2(acc, a, b) \
    asm("fma.rn.f32x2 %0, %1, %2, %3;" : "=l"(acc) : "l"(a), "l"(b), "l"(acc))

// SMEM layout (bytes):
//  A_s : u64 [64][34]  duplicated gathered features, A_s[kk][r] = (a,a)  -> 17408 B
//  B_s : f32 [64*128]  contiguous copy of W chunk                        -> 32768 B
//  srcsh[32], validsh[32]                                                ->   256 B
#define A_STRIDE 34
#define A_BYTES  (64 * A_STRIDE * 8)
#define B_BYTES  (64 * 128 * 4)
#define SMEM_BYTES (A_BYTES + B_BYTES + 64 * 4)

__global__ __launch_bounds__(128, 2)
void dpc_main_kernel(const float* __restrict__ features,
                     const void*  __restrict__ vidx,
                     const int*   __restrict__ num_list,
                     const float* __restrict__ Wm,
                     const float* __restrict__ gamma,
                     const float* __restrict__ beta,
                     float* __restrict__ out_feat,
                     int N, int M, int K3, int B, int K, int R)
{
    extern __shared__ unsigned long long smem[];
    unsigned long long* As = smem;                                   // [64][A_STRIDE]
    float* Bs   = (float*)(smem + 64 * A_STRIDE);                    // [64*128]
    int* srcsh  = (int*)((char*)smem + A_BYTES + B_BYTES);
    int* validsh = srcsh + 32;

    const int tid  = threadIdx.x;
    const int wid  = tid >> 5;     // 0..3 : row group (rows wid*8..wid*8+7)
    const int lane = tid & 31;     // column group (cols lane*4..lane*4+3)
    const int row0 = blockIdx.x * 32;
    const int is64 = g_idx_is64;

    // --- per-block source rows + validity ---
    if (tid < 32) {
        int grow = row0 + tid;
        int src = 0, valid = 0;
        if (grow < R) {
            int b = grow / K;
            int j = grow - b * K;
            int off = 0;
            for (int t = 0; t < b; ++t) off += num_list[t];
            int end = min(num_list[b], K);
            valid = (j < end) ? 1 : 0;
            int s = off + j;
            src = max(0, min(s, M - 1));
        }
        srcsh[tid]   = src;
        validsh[tid] = valid;
    }

    unsigned long long acc[8][2];
#pragma unroll
    for (int j = 0; j < 8; ++j) { acc[j][0] = 0ull; acc[j][1] = 0ull; }

    const long long* vidx64 = (const long long*)vidx;
    const int*       vidx32 = (const int*)vidx;

    __syncthreads();

    for (int n = 0; n < K3; ++n) {
        if (n) __syncthreads();   // compute of previous chunk done before overwrite

        // ---- stage B: contiguous copy of W rows [n*64, n*64+64), all 128 cols ----
        {
            const float* Wsrc = Wm + (size_t)n * 64 * 128;
#pragma unroll
            for (int i = 0; i < 16; ++i) {
                float4 v = *(const float4*)(Wsrc + tid * 4 + i * 512);
                *(float4*)(Bs + tid * 4 + i * 512) = v;
            }
        }

        // ---- stage A: row = lane, column quarter = wid (16 floats), duplicated ----
        {
            int src = srcsh[lane];
            long long idx = is64 ? vidx64[(size_t)src * K3 + n]
                                 : (long long)vidx32[src * K3 + n];
            bool ok = (idx >= 0);
            long long ii = ok ? ((idx < (long long)(N - 1)) ? idx : (long long)(N - 1)) : 0;
            const float* frow = features + ii * 64 + wid * 16;
#pragma unroll
            for (int i = 0; i < 4; ++i) {
                float4 v = make_float4(0.f, 0.f, 0.f, 0.f);
                if (ok) v = *(const float4*)(frow + i * 4);
                int kk0 = wid * 16 + i * 4;
                unsigned a0 = smaddr(&As[(kk0 + 0) * A_STRIDE + lane]);
                unsigned a1 = smaddr(&As[(kk0 + 1) * A_STRIDE + lane]);
                unsigned a2 = smaddr(&As[(kk0 + 2) * A_STRIDE + lane]);
                unsigned a3 = smaddr(&As[(kk0 + 3) * A_STRIDE + lane]);
                asm volatile("st.shared.v2.b32 [%0], {%1,%1};" :: "r"(a0), "r"(__float_as_uint(v.x)));
                asm volatile("st.shared.v2.b32 [%0], {%1,%1};" :: "r"(a1), "r"(__float_as_uint(v.y)));
                asm volatile("st.shared.v2.b32 [%0], {%1,%1};" :: "r"(a2), "r"(__float_as_uint(v.z)));
                asm volatile("st.shared.v2.b32 [%0], {%1,%1};" :: "r"(a3), "r"(__float_as_uint(v.w)));
            }
        }
        __syncthreads();

        // ---- compute: per k-step 4 broadcast v2.b64 (A) + 1 coalesced v2.b64 (B)
        //      + 16 FFMA2 ----
        const unsigned abase = smaddr(&As[wid * 8]);          // + kk*A_STRIDE*8
        const unsigned bbase = smaddr(&Bs[lane * 4]);         // + kk*128*4
#pragma unroll 8
        for (int kk = 0; kk < 64; ++kk) {
            unsigned long long b01, b23;
            asm("ld.shared.v2.b64 {%0,%1}, [%2];"
                : "=l"(b01), "=l"(b23) : "r"(bbase + kk * 512));
            unsigned long long a0, a1, a2, a3, a4, a5, a6, a7;
            unsigned ab = abase + kk * (A_STRIDE * 8);
            asm("ld.shared.v2.b64 {%0,%1}, [%2];" : "=l"(a0), "=l"(a1) : "r"(ab));
            asm("ld.shared.v2.b64 {%0,%1}, [%2];" : "=l"(a2), "=l"(a3) : "r"(ab + 16));
            asm("ld.shared.v2.b64 {%0,%1}, [%2];" : "=l"(a4), "=l"(a5) : "r"(ab + 32));
            asm("ld.shared.v2.b64 {%0,%1}, [%2];" : "=l"(a6), "=l"(a7) : "r"(ab + 48));
            FMA2(acc[0][0], a0, b01); FMA2(acc[0][1], a0, b23);
            FMA2(acc[1][0], a1, b01); FMA2(acc[1][1], a1, b23);
            FMA2(acc[2][0], a2, b01); FMA2(acc[2][1], a2, b23);
            FMA2(acc[3][0], a3, b01); FMA2(acc[3][1], a3, b23);
            FMA2(acc[4][0], a4, b01); FMA2(acc[4][1], a4, b23);
            FMA2(acc[5][0], a5, b01); FMA2(acc[5][1], a5, b23);
            FMA2(acc[6][0], a6, b01); FMA2(acc[6][1], a6, b23);
            FMA2(acc[7][0], a7, b01); FMA2(acc[7][1], a7, b23);
        }
    }

    // ---- epilogue: warp-shuffle LayerNorm + ReLU straight from registers ----
    float4 gmv = *(const float4*)(gamma + lane * 4);
    float4 btv = *(const float4*)(beta + lane * 4);

#pragma unroll
    for (int j = 0; j < 8; ++j) {
        int row  = wid * 8 + j;
        int grow = row0 + row;
        float2 v01, v23;
        asm("mov.b64 {%0,%1}, %2;" : "=f"(v01.x), "=f"(v01.y) : "l"(acc[j][0]));
        asm("mov.b64 {%0,%1}, %2;" : "=f"(v23.x), "=f"(v23.y) : "l"(acc[j][1]));
        float s  = v01.x + v01.y + v23.x + v23.y;
        float sq = v01.x * v01.x + v01.y * v01.y + v23.x * v23.x + v23.y * v23.y;
#pragma unroll
        for (int o = 16; o; o >>= 1) {
            s  += __shfl_xor_sync(0xffffffffu, s,  o);
            sq += __shfl_xor_sync(0xffffffffu, sq, o);
        }
        float mu   = s * (1.f / 128.f);
        float var  = sq * (1.f / 128.f) - mu * mu;
        float rstd = rsqrtf(var + 1e-3f);
        float4 y;
        if (validsh[row]) {
            y.x = fmaxf((v01.x - mu) * rstd * gmv.x + btv.x, 0.f);
            y.y = fmaxf((v01.y - mu) * rstd * gmv.y + btv.y, 0.f);
            y.z = fmaxf((v23.x - mu) * rstd * gmv.z + btv.z, 0.f);
            y.w = fmaxf((v23.y - mu) * rstd * gmv.w + btv.w, 0.f);
        } else {
            y = make_float4(0.f, 0.f, 0.f, 0.f);
        }
        if (grow < R)
            *(float4*)(out_feat + (size_t)grow * 128 + lane * 4) = y;
    }
}

__global__ void dpc_coords_kernel(const float* __restrict__ center,
                                  const int* __restrict__ num_list,
                                  float* __restrict__ out_coor,
                                  int B, int K, int M, int R)
{
    int i = blockIdx.x * blockDim.x + threadIdx.x;
    if (i >= R) return;
    int b = i / K;
    int j = i - b * K;
    int off = 0;
    for (int t = 0; t < b; ++t) off += num_list[t];
    int end   = min(num_list[b], K);
    int valid = (j < end) ? 1 : 0;
    int s = off + j;
    s = max(0, min(s, M - 1));
    float x = 0.f, y = 0.f, z = 0.f;
    if (valid) {
        x = center[s * 3 + 0];
        y = center[s * 3 + 1];
        z = center[s * 3 + 2];
    }
    float c0 = (b < B - 1) ? (float)(b + 1) : 0.f;
    float4 o = make_float4(c0, x, y, z);
    *(float4*)(out_coor + (size_t)i * 4) = o;
}

extern "C" void kernel_launch(void* const* d_in, const int* in_sizes, int n_in,
                              void* d_out, int out_size) {
    const float* features = (const float*)d_in[0];
    const float* center   = (const float*)d_in[1];
    const void*  vidx     = d_in[2];
    const int*   num_list = (const int*)d_in[3];
    const float* Wm       = (const float*)d_in[4];
    const float* gamma    = (const float*)d_in[5];
    const float* beta     = (const float*)d_in[6];

    int C_OUT = in_sizes[5];                       // 128
    int M     = in_sizes[1] / 3;                   // 40000
    int K3    = in_sizes[2] / M;                   // 27
    int C_IN  = in_sizes[4] / (C_OUT * K3);        // 64
    int N     = in_sizes[0] / C_IN;                // 200000
    int B     = in_sizes[3];                       // 4
    int K     = out_size / (B * (C_OUT + 4));      // 2048
    int R     = B * K;                             // 8192

    float* out_feat = (float*)d_out;
    float* out_coor = out_feat + (size_t)R * C_OUT;

    detect_idx_dtype<<<1, 1>>>(vidx, in_sizes[2], N);

    cudaFuncSetAttribute(dpc_main_kernel,
                         cudaFuncAttributeMaxDynamicSharedMemorySize, SMEM_BYTES);
    dpc_main_kernel<<<(R + 31) / 32, 128, SMEM_BYTES>>>(
        features, vidx, num_list, Wm, gamma, beta, out_feat,
        N, M, K3, B, K, R);

    dpc_coords_kernel<<<(R + 255) / 256, 256>>>(center, num_list, out_coor, B, K, M, R);
}

// round 7
// speedup vs baseline: 3.4548x; 2.3500x over previous
#include <cuda_runtime.h>
#include <cuda_bf16.h>
#include <cstdint>

// ---------------------------------------------------------------------------
// DynamicPointConvBackBone via classic mma.sync (valid PTX for compute_103).
// Only the 8192 resampled rows are observable -> gather + [8192,1728]x[1728,128]
// GEMM + LayerNorm + ReLU on those rows only.
// GEMM: mma.sync.aligned.m16n8k16 bf16 with 2-term split (hi/lo), 3 mma terms
// per tile (AhiBhi + AloBhi + AhiBlo) -> fp32-class accuracy (~1e-5 rel).
// W pre-permuted in GMEM to exact fragment order -> no ldmatrix needed.
// K split by 2 across CTAs (128 CTAs, one wave); reduce+LN fused kernel.
// ---------------------------------------------------------------------------

#define COUT   128
#define KTOTAL 1728
#define NK16   (KTOTAL / 16)        // 108
#define NCHUNK (KTOTAL / 32)        // 54 chunks of 32 k
#define HCHUNK (NCHUNK / 2)         // 27 per K-split
#define RMAX   8192

__device__ unsigned g_Bhi[NK16 * 1024];   // [k16][np(8)][lane(32)][4 words]
__device__ unsigned g_Blo[NK16 * 1024];
__device__ float    g_part[2u * RMAX * COUT];   // [split][row][col]
__device__ int      g_idx_is64;

// ---------------------------------------------------------------------------
// prep: W [1728,128] -> bf16 hi/lo in per-fragment order; also idx dtype detect.
// word linear index = ((t*8 + np)*32 + lane)*4 + wsel
//   n8 = np*2 + (wsel>>1), breg = wsel&1, g = lane>>2, tg = lane&3
//   k0 = t*16 + breg*8 + tg*2 ; n = n8*8 + g ; word = bf16x2(W[k0][n], W[k0+1][n])
// ---------------------------------------------------------------------------
__global__ void prep_w_kernel(const float* __restrict__ W,
                              const void* __restrict__ vidx, int ne, int N)
{
    int tid = blockIdx.x * blockDim.x + threadIdx.x;
    if (tid == 0) {
        const long long* p = (const long long*)vidx;
        int cnt = (ne >= 16) ? 8 : (ne / 2);
        int ok = (cnt > 0) ? 1 : 0;
        for (int i = 0; i < cnt; ++i) {
            long long v = p[i];
            if (v < -(long long)N || v >= (long long)N) ok = 0;
        }
        g_idx_is64 = ok;
    }
    if (tid >= NK16 * 1024) return;
    int wsel = tid & 3;
    int lane = (tid >> 2) & 31;
    int np   = (tid >> 7) & 7;
    int t    = tid >> 10;
    int n8   = np * 2 + (wsel >> 1);
    int breg = wsel & 1;
    int g    = lane >> 2, tg = lane & 3;
    int k0   = t * 16 + breg * 8 + tg * 2;
    int n    = n8 * 8 + g;
    float v0 = W[(size_t)k0 * COUT + n];
    float v1 = W[(size_t)(k0 + 1) * COUT + n];
    __nv_bfloat16 h0 = __float2bfloat16_rn(v0);
    __nv_bfloat16 h1 = __float2bfloat16_rn(v1);
    float l0 = v0 - __bfloat162float(h0);
    float l1 = v1 - __bfloat162float(h1);
    __nv_bfloat162 hp = __halves2bfloat162(h0, h1);
    __nv_bfloat162 lp = __halves2bfloat162(__float2bfloat16_rn(l0),
                                           __float2bfloat16_rn(l1));
    g_Bhi[tid] = *(unsigned*)&hp;
    g_Blo[tid] = *(unsigned*)&lp;
}

// ---------------------------------------------------------------------------
// main GEMM kernel. Grid (64, 2): x = 128-row block, y = K split.
// 256 threads = 8 warps; warp tile 32 rows x 64 cols (mh = wid>>1, nh = wid&1).
// SMEM (32 KB): A_hi/A_lo: [k16b(2)][mb(8)][lane][16B]; B_hi/B_lo:
//               [k16b(2)][np(8)][lane][16B].
// ---------------------------------------------------------------------------
#define A_HI_W 0
#define A_LO_W 2048
#define B_HI_W 4096
#define B_LO_W 6144

#define MMA(d, a, b0v, b1v) \
    asm("mma.sync.aligned.m16n8k16.row.col.f32.bf16.bf16.f32 " \
        "{%0,%1,%2,%3}, {%4,%5,%6,%7}, {%8,%9}, {%0,%1,%2,%3};" \
        : "+f"((d)[0]), "+f"((d)[1]), "+f"((d)[2]), "+f"((d)[3]) \
        : "r"((a).x), "r"((a).y), "r"((a).z), "r"((a).w), "r"(b0v), "r"(b1v))

__global__ __launch_bounds__(256, 1)
void dpc_mma_kernel(const float* __restrict__ features,
                    const void*  __restrict__ vidx,
                    const int*   __restrict__ num_list,
                    int N, int M, int K3, int C_IN, int Kq, int R)
{
    __shared__ unsigned smw[8192];   // 32 KB

    const int tid  = threadIdx.x;
    const int wid  = tid >> 5;
    const int lane = tid & 31;
    const int g    = lane >> 2;
    const int tg   = lane & 3;
    const int mh   = wid >> 1;    // 0..3 : 32-row group
    const int nh   = wid & 1;     // 0..1 : 64-col group
    const int s    = blockIdx.y;
    const int row0 = blockIdx.x * 128;
    const int is64 = g_idx_is64;

    // staging identity: this thread stages row r, k-half h of each chunk
    const int r   = tid >> 1;
    const int h   = tid & 1;
    const int mb_ = r >> 4;
    const int g7  = r & 7;
    const int rrw = (r & 15) >> 3;

    // source row for gather (fixed per thread)
    int srcrow;
    {
        int grow = row0 + r;
        int b = grow / Kq;
        int off = 0;
        for (int t = 0; t < b; ++t) off += num_list[t];
        srcrow = max(0, min(off + (grow - b * Kq), M - 1));
    }

    const long long* vidx64 = (const long long*)vidx;
    const int*       vidx32 = (const int*)vidx;

    const int cbeg = s * HCHUNK;
    const int cend = cbeg + HCHUNK;

    float acc[2][8][4];
#pragma unroll
    for (int mi = 0; mi < 2; ++mi)
#pragma unroll
        for (int p = 0; p < 8; ++p)
#pragma unroll
            for (int q = 0; q < 4; ++q) acc[mi][p][q] = 0.f;

    // prefetch registers
    float4 av[4];
    uint4  bhv[2], blv[2];
    int    okA;

    // ---- prefetch chunk c into registers ----
    auto prefetch = [&](int c) {
        int nn = c >> 1;
        int ko = (c & 1) * 32 + h * 16;
        long long idx = is64 ? vidx64[(size_t)srcrow * K3 + nn]
                             : (long long)vidx32[srcrow * K3 + nn];
        okA = (idx >= 0);
        long long ii = okA ? ((idx < (long long)(N - 1)) ? idx : (long long)(N - 1)) : 0;
        const float* fr = features + ii * C_IN + ko;
#pragma unroll
        for (int i = 0; i < 4; ++i) av[i] = *(const float4*)(fr + i * 4);
#pragma unroll
        for (int kb = 0; kb < 2; ++kb) {
            bhv[kb] = *(const uint4*)(g_Bhi + (size_t)(c * 2 + kb) * 1024 + tid * 4);
            blv[kb] = *(const uint4*)(g_Blo + (size_t)(c * 2 + kb) * 1024 + tid * 4);
        }
    };

    prefetch(cbeg);

    for (int c = cbeg; c < cend; ++c) {
        // ---- STS staged regs: A with bf16 hi/lo split into fragment layout ----
#pragma unroll
        for (int i = 0; i < 8; ++i) {
            float v0, v1;
            float4 q = av[i >> 1];
            if (i & 1) { v0 = q.z; v1 = q.w; } else { v0 = q.x; v1 = q.y; }
            if (!okA) { v0 = 0.f; v1 = 0.f; }
            __nv_bfloat16 b0 = __float2bfloat16_rn(v0);
            __nv_bfloat16 b1 = __float2bfloat16_rn(v1);
            float l0 = v0 - __bfloat162float(b0);
            float l1 = v1 - __bfloat162float(b1);
            __nv_bfloat162 hp = __halves2bfloat162(b0, b1);
            __nv_bfloat162 lp = __halves2bfloat162(__float2bfloat16_rn(l0),
                                                   __float2bfloat16_rn(l1));
            int waddr = ((h * 8 + mb_) * 32 + g7 * 4 + (i & 3)) * 4 + rrw + 2 * (i >> 2);
            smw[A_HI_W + waddr] = *(unsigned*)&hp;
            smw[A_LO_W + waddr] = *(unsigned*)&lp;
        }
#pragma unroll
        for (int kb = 0; kb < 2; ++kb) {
            ((uint4*)(smw + B_HI_W))[kb * 256 + tid] = bhv[kb];
            ((uint4*)(smw + B_LO_W))[kb * 256 + tid] = blv[kb];
        }
        __syncthreads();

        if (c + 1 < cend) prefetch(c + 1);   // latency overlapped with MMAs

        // ---- compute chunk (2 k16 steps) ----
#pragma unroll
        for (int kb = 0; kb < 2; ++kb) {
            uint4 ahi[2], alo[2];
#pragma unroll
            for (int mi = 0; mi < 2; ++mi) {
                int aw = ((kb * 8 + mh * 2 + mi) * 32 + lane) * 4;
                ahi[mi] = *(const uint4*)(smw + A_HI_W + aw);
                alo[mi] = *(const uint4*)(smw + A_LO_W + aw);
            }
#pragma unroll
            for (int pi = 0; pi < 4; ++pi) {
                int bw = ((kb * 8 + nh * 4 + pi) * 32 + lane) * 4;
                uint4 bh = *(const uint4*)(smw + B_HI_W + bw);
                uint4 bl = *(const uint4*)(smw + B_LO_W + bw);
#pragma unroll
                for (int mi = 0; mi < 2; ++mi) {
                    MMA(acc[mi][pi * 2],     ahi[mi], bh.x, bh.y);
                    MMA(acc[mi][pi * 2],     alo[mi], bh.x, bh.y);
                    MMA(acc[mi][pi * 2],     ahi[mi], bl.x, bl.y);
                    MMA(acc[mi][pi * 2 + 1], ahi[mi], bh.z, bh.w);
                    MMA(acc[mi][pi * 2 + 1], alo[mi], bh.z, bh.w);
                    MMA(acc[mi][pi * 2 + 1], ahi[mi], bl.z, bl.w);
                }
            }
        }
        __syncthreads();
    }

    // ---- store partials ----
    float* part = g_part + (size_t)s * R * COUT;
#pragma unroll
    for (int mi = 0; mi < 2; ++mi) {
        int rA = row0 + mh * 32 + mi * 16 + g;
#pragma unroll
        for (int p = 0; p < 8; ++p) {
            int col = nh * 64 + p * 8 + tg * 2;
            *(float2*)&part[(size_t)rA * COUT + col] =
                make_float2(acc[mi][p][0], acc[mi][p][1]);
            *(float2*)&part[(size_t)(rA + 8) * COUT + col] =
                make_float2(acc[mi][p][2], acc[mi][p][3]);
        }
    }
}

// ---------------------------------------------------------------------------
// reduce partials + LayerNorm + ReLU + validity zeroing. One warp per row.
// ---------------------------------------------------------------------------
__global__ void reduce_ln_kernel(const float* __restrict__ gamma,
                                 const float* __restrict__ beta,
                                 const int* __restrict__ num_list,
                                 float* __restrict__ out_feat,
                                 int B, int Kq, int R)
{
    int wid  = threadIdx.x >> 5;
    int lane = threadIdx.x & 31;
    int row  = blockIdx.x * 8 + wid;
    if (row >= R) return;

    const float* p0 = g_part + (size_t)row * COUT + lane * 4;
    float4 a = *(const float4*)p0;
    float4 b = *(const float4*)(p0 + (size_t)R * COUT);
    float4 v = make_float4(a.x + b.x, a.y + b.y, a.z + b.z, a.w + b.w);

    float s  = v.x + v.y + v.z + v.w;
    float sq = v.x * v.x + v.y * v.y + v.z * v.z + v.w * v.w;
#pragma unroll
    for (int o = 16; o; o >>= 1) {
        s  += __shfl_xor_sync(0xffffffffu, s,  o);
        sq += __shfl_xor_sync(0xffffffffu, sq, o);
    }
    float mu   = s * (1.f / 128.f);
    float var  = sq * (1.f / 128.f) - mu * mu;
    float rstd = rsqrtf(var + 1e-3f);

    int bb = row / Kq;
    int j  = row - bb * Kq;
    int valid = (j < min(num_list[bb], Kq)) ? 1 : 0;

    float4 gm = *(const float4*)(gamma + lane * 4);
    float4 bt = *(const float4*)(beta  + lane * 4);
    float4 y;
    if (valid) {
        y.x = fmaxf((v.x - mu) * rstd * gm.x + bt.x, 0.f);
        y.y = fmaxf((v.y - mu) * rstd * gm.y + bt.y, 0.f);
        y.z = fmaxf((v.z - mu) * rstd * gm.z + bt.z, 0.f);
        y.w = fmaxf((v.w - mu) * rstd * gm.w + bt.w, 0.f);
    } else {
        y = make_float4(0.f, 0.f, 0.f, 0.f);
    }
    *(float4*)(out_feat + (size_t)row * COUT + lane * 4) = y;
}

__global__ void dpc_coords_kernel(const float* __restrict__ center,
                                  const int* __restrict__ num_list,
                                  float* __restrict__ out_coor,
                                  int B, int Kq, int M, int R)
{
    int i = blockIdx.x * blockDim.x + threadIdx.x;
    if (i >= R) return;
    int b = i / Kq;
    int j = i - b * Kq;
    int off = 0;
    for (int t = 0; t < b; ++t) off += num_list[t];
    int valid = (j < min(num_list[b], Kq)) ? 1 : 0;
    int sidx = max(0, min(off + j, M - 1));
    float x = 0.f, y = 0.f, z = 0.f;
    if (valid) {
        x = center[sidx * 3 + 0];
        y = center[sidx * 3 + 1];
        z = center[sidx * 3 + 2];
    }
    float c0 = (b < B - 1) ? (float)(b + 1) : 0.f;
    *(float4*)(out_coor + (size_t)i * 4) = make_float4(c0, x, y, z);
}

extern "C" void kernel_launch(void* const* d_in, const int* in_sizes, int n_in,
                              void* d_out, int out_size) {
    const float* features = (const float*)d_in[0];
    const float* center   = (const float*)d_in[1];
    const void*  vidx     = d_in[2];
    const int*   num_list = (const int*)d_in[3];
    const float* Wm       = (const float*)d_in[4];
    const float* gamma    = (const float*)d_in[5];
    const float* beta     = (const float*)d_in[6];

    int C_OUT = in_sizes[5];                       // 128
    int M     = in_sizes[1] / 3;                   // 40000
    int K3    = in_sizes[2] / M;                   // 27
    int C_IN  = in_sizes[4] / (C_OUT * K3);        // 64
    int N     = in_sizes[0] / C_IN;                // 200000
    int B     = in_sizes[3];                       // 4
    int Kq    = out_size / (B * (C_OUT + 4));      // 2048
    int R     = B * Kq;                            // 8192

    float* out_feat = (float*)d_out;
    float* out_coor = out_feat + (size_t)R * C_OUT;

    // Launch order so ncu -s 5 -c 1 lands on the MAIN kernel
    // (4 launches/replay: prep(0) main(1) reduce(2) coords(3); idx5 = main).
    prep_w_kernel<<<(NK16 * 1024 + 255) / 256, 256>>>(Wm, vidx, in_sizes[2], N);

    dim3 grid((R + 127) / 128, 2);
    dpc_mma_kernel<<<grid, 256>>>(features, vidx, num_list,
                                  N, M, K3, C_IN, Kq, R);

    reduce_ln_kernel<<<(R + 7) / 8, 256>>>(gamma, beta, num_list, out_feat, B, Kq, R);

    dpc_coords_kernel<<<(R + 255) / 256, 256>>>(center, num_list, out_coor, B, Kq, M, R);
}

// round 9
// speedup vs baseline: 4.0217x; 1.1641x over previous
#include <cuda_runtime.h>
#include <cuda_fp16.h>
#include <cstdint>

// ---------------------------------------------------------------------------
// DynamicPointConvBackBone via classic mma.sync m16n8k16 fp16 (compute_103-safe).
// Only the 8192 resampled rows are observable -> gather + [8192,1728]x[1728,128]
// GEMM + LayerNorm + ReLU on those rows only, fully fused in ONE main kernel.
// Precision: W scaled by 2^13 (unscaled before LN), A split fp16 hi+lo,
// B single fp16 -> 2 MMA terms (AhB + AlB), expected rel_err ~1e-4.
// 64-row tiles x 128 CTAs, full K per CTA (no partials, no reduce kernel).
// W pre-permuted to exact fragment order in GMEM -> no ldmatrix.
// ---------------------------------------------------------------------------

#define COUT   128
#define KTOTAL 1728
#define NK16   (KTOTAL / 16)        // 108
#define NCHUNK (KTOTAL / 32)        // 54
#define WSCALE 8192.0f
#define WINV   (1.0f / 8192.0f)

__device__ unsigned g_Bh[NK16 * 1024];   // [k16][np(8)][lane(32)][4 words] fp16x2
__device__ int      g_idx_is64;

// ---------------------------------------------------------------------------
// prep: W [1728,128] * 2^13 -> fp16x2 words in per-fragment order; idx detect.
// word index = ((t*8 + np)*32 + lane)*4 + wsel
//   n8 = np*2 + (wsel>>1), breg = wsel&1, g = lane>>2, tg = lane&3
//   k0 = t*16 + breg*8 + tg*2 ; n = n8*8 + g ; word = h2(W[k0][n], W[k0+1][n])
// ---------------------------------------------------------------------------
__global__ void prep_w_kernel(const float* __restrict__ W,
                              const void* __restrict__ vidx, int ne, int N)
{
    int tid = blockIdx.x * blockDim.x + threadIdx.x;
    if (tid == 0) {
        const long long* p = (const long long*)vidx;
        int cnt = (ne >= 16) ? 8 : (ne / 2);
        int ok = (cnt > 0) ? 1 : 0;
        for (int i = 0; i < cnt; ++i) {
            long long v = p[i];
            if (v < -(long long)N || v >= (long long)N) ok = 0;
        }
        g_idx_is64 = ok;
    }
    if (tid >= NK16 * 1024) return;
    int wsel = tid & 3;
    int lane = (tid >> 2) & 31;
    int np   = (tid >> 7) & 7;
    int t    = tid >> 10;
    int n8   = np * 2 + (wsel >> 1);
    int breg = wsel & 1;
    int g    = lane >> 2, tg = lane & 3;
    int k0   = t * 16 + breg * 8 + tg * 2;
    int n    = n8 * 8 + g;
    float v0 = W[(size_t)k0 * COUT + n] * WSCALE;
    float v1 = W[(size_t)(k0 + 1) * COUT + n] * WSCALE;
    __half2 hp = __halves2half2(__float2half_rn(v0), __float2half_rn(v1));
    g_Bh[tid] = *(unsigned*)&hp;
}

#define MMA(d, a, b0v, b1v) \
    asm("mma.sync.aligned.m16n8k16.row.col.f32.f16.f16.f32 " \
        "{%0,%1,%2,%3}, {%4,%5,%6,%7}, {%8,%9}, {%0,%1,%2,%3};" \
        : "+f"((d)[0]), "+f"((d)[1]), "+f"((d)[2]), "+f"((d)[3]) \
        : "r"((a).x), "r"((a).y), "r"((a).z), "r"((a).w), "r"(b0v), "r"(b1v))

// ---------------------------------------------------------------------------
// main kernel. 128 CTAs x 256 threads; CTA tile 64 rows x 128 cols, full K.
// Warp tile 16 rows x 64 cols (mh = wid>>1 row group, nh = wid&1 col half).
// Double-buffered SMEM stages; epilogue does LN + ReLU + coords.
// ---------------------------------------------------------------------------
__global__ __launch_bounds__(256, 1)
void dpc_mma_kernel(const float* __restrict__ features,
                    const void*  __restrict__ vidx,
                    const int*   __restrict__ num_list,
                    const float* __restrict__ center,
                    const float* __restrict__ gamma,
                    const float* __restrict__ beta,
                    float* __restrict__ out_feat,
                    float* __restrict__ out_coor,
                    int N, int M, int K3, int C_IN, int B, int Kq, int R)
{
    __shared__ unsigned smA_h[2][1024];   // [buf][(kb*4+mb)*32+lane][4]
    __shared__ unsigned smA_l[2][1024];
    __shared__ unsigned smB[2][2048];     // [buf][(kb*8+np)*32+lane][4]
    __shared__ float    red[64][4];       // [row][{s,q} x nh]
    __shared__ float2   musg[64];
    __shared__ int      validsh[64];

    const int tid  = threadIdx.x;
    const int wid  = tid >> 5;
    const int lane = tid & 31;
    const int ga   = lane >> 2;
    const int tg   = lane & 3;
    const int mh   = wid >> 1;     // 0..3
    const int nh   = wid & 1;      // 0..1
    const int row0 = blockIdx.x * 64;
    const int is64 = g_idx_is64;

    // staging roles
    const bool isA = (tid < 128);
    const int  r   = tid >> 1;        // A: row in block 0..63
    const int  h   = tid & 1;         // A: k-half of the 32-chunk
    const int  mb  = r >> 4;
    const int  g7  = r & 7;
    const int  rrw = (r & 15) >> 3;
    const int  bq  = tid - 128;       // B: 0..127

    // source row for gather (fixed per A-thread)
    int srcrow = 0;
    if (isA) {
        int grow = row0 + r;
        int b = grow / Kq;
        int off = 0;
        for (int t = 0; t < b; ++t) off += num_list[t];
        srcrow = max(0, min(off + (grow - b * Kq), M - 1));
    }

    const long long* vidx64 = (const long long*)vidx;
    const int*       vidx32 = (const int*)vidx;

    float acc[8][4];
#pragma unroll
    for (int p = 0; p < 8; ++p)
#pragma unroll
        for (int q = 0; q < 4; ++q) acc[p][q] = 0.f;

    float4 av[4];
    uint4  bhv[4];
    int    okA = 0;

    auto pref = [&](int c) {
        if (isA) {
            int nn = c >> 1;
            int ko = ((c & 1) << 5) + (h << 4);
            long long idx = is64 ? vidx64[(size_t)srcrow * K3 + nn]
                                 : (long long)vidx32[srcrow * K3 + nn];
            okA = (idx >= 0);
            if (okA) {
                long long ii = (idx < (long long)(N - 1)) ? idx : (long long)(N - 1);
                const float* fr = features + ii * C_IN + ko;
#pragma unroll
                for (int i = 0; i < 4; ++i) av[i] = *(const float4*)(fr + i * 4);
            } else {
#pragma unroll
                for (int i = 0; i < 4; ++i) av[i] = make_float4(0.f, 0.f, 0.f, 0.f);
            }
        } else {
            const uint4* src = (const uint4*)g_Bh + (size_t)c * 512;
#pragma unroll
            for (int j = 0; j < 4; ++j) bhv[j] = src[bq + j * 128];
        }
    };

    auto stage = [&](int buf) {
        if (isA) {
#pragma unroll
            for (int i = 0; i < 8; ++i) {
                float4 q = av[i >> 1];
                float v0 = (i & 1) ? q.z : q.x;
                float v1 = (i & 1) ? q.w : q.y;
                __half h0 = __float2half_rn(v0);
                __half h1 = __float2half_rn(v1);
                float l0 = v0 - __half2float(h0);
                float l1 = v1 - __half2float(h1);
                __half2 hp = __halves2half2(h0, h1);
                __half2 lp = __halves2half2(__float2half_rn(l0), __float2half_rn(l1));
                int waddr = ((h * 4 + mb) * 32 + g7 * 4 + (i & 3)) * 4
                            + rrw + 2 * (i >> 2);
                smA_h[buf][waddr] = *(unsigned*)&hp;
                smA_l[buf][waddr] = *(unsigned*)&lp;
            }
        } else {
#pragma unroll
            for (int j = 0; j < 4; ++j)
                ((uint4*)smB[buf])[bq + j * 128] = bhv[j];
        }
    };

    // prologue
    pref(0);
    stage(0);
    __syncthreads();

    for (int c = 0; c < NCHUNK; ++c) {
        const int buf = c & 1;
        if (c + 1 < NCHUNK) pref(c + 1);   // LDG overlapped with MMAs below

        // ---- compute chunk: 12 LDS.128 + 32 MMAs per warp ----
#pragma unroll
        for (int kb = 0; kb < 2; ++kb) {
            uint4 ah = *(const uint4*)&smA_h[buf][((kb * 4 + mh) * 32 + lane) * 4];
            uint4 al = *(const uint4*)&smA_l[buf][((kb * 4 + mh) * 32 + lane) * 4];
#pragma unroll
            for (int pi = 0; pi < 4; ++pi) {
                uint4 b = *(const uint4*)&smB[buf][((kb * 8 + nh * 4 + pi) * 32 + lane) * 4];
                MMA(acc[pi * 2],     ah, b.x, b.y);
                MMA(acc[pi * 2],     al, b.x, b.y);
                MMA(acc[pi * 2 + 1], ah, b.z, b.w);
                MMA(acc[pi * 2 + 1], al, b.z, b.w);
            }
        }

        if (c + 1 < NCHUNK) stage(buf ^ 1);
        __syncthreads();
    }

    // ---- epilogue: unscale, row reduce, LayerNorm + ReLU, store ----
    float s0 = 0.f, q0 = 0.f, s1 = 0.f, q1 = 0.f;
#pragma unroll
    for (int p = 0; p < 8; ++p) {
        acc[p][0] *= WINV; acc[p][1] *= WINV;
        acc[p][2] *= WINV; acc[p][3] *= WINV;
        s0 += acc[p][0] + acc[p][1];
        q0 += acc[p][0] * acc[p][0] + acc[p][1] * acc[p][1];
        s1 += acc[p][2] + acc[p][3];
        q1 += acc[p][2] * acc[p][2] + acc[p][3] * acc[p][3];
    }
#pragma unroll
    for (int o = 1; o <= 2; o <<= 1) {
        s0 += __shfl_xor_sync(0xffffffffu, s0, o);
        q0 += __shfl_xor_sync(0xffffffffu, q0, o);
        s1 += __shfl_xor_sync(0xffffffffu, s1, o);
        q1 += __shfl_xor_sync(0xffffffffu, q1, o);
    }
    if (tg == 0) {
        red[mh * 16 + ga][nh * 2]         = s0;
        red[mh * 16 + ga][nh * 2 + 1]     = q0;
        red[mh * 16 + ga + 8][nh * 2]     = s1;
        red[mh * 16 + ga + 8][nh * 2 + 1] = q1;
    }
    __syncthreads();

    if (tid < 64) {
        float s = red[tid][0] + red[tid][2];
        float q = red[tid][1] + red[tid][3];
        float mu  = s * (1.f / 128.f);
        float var = q * (1.f / 128.f) - mu * mu;
        musg[tid] = make_float2(mu, rsqrtf(var + 1e-3f));
        int grow = row0 + tid;
        int b = grow / Kq;
        int j = grow - b * Kq;
        validsh[tid] = (j < min(num_list[b], Kq)) ? 1 : 0;
    }
    __syncthreads();

    {
        int rowa = mh * 16 + ga;
        float2 ma = musg[rowa], mb2 = musg[rowa + 8];
        int va_ = validsh[rowa], vb_ = validsh[rowa + 8];
        float* oA = out_feat + (size_t)(row0 + rowa) * COUT;
        float* oB = oA + 8 * COUT;
#pragma unroll
        for (int p = 0; p < 8; ++p) {
            int col = nh * 64 + p * 8 + tg * 2;
            float2 gm = *(const float2*)(gamma + col);
            float2 bt = *(const float2*)(beta + col);
            float2 ya, yb;
            if (va_) {
                ya.x = fmaxf((acc[p][0] - ma.x) * ma.y * gm.x + bt.x, 0.f);
                ya.y = fmaxf((acc[p][1] - ma.x) * ma.y * gm.y + bt.y, 0.f);
            } else ya = make_float2(0.f, 0.f);
            if (vb_) {
                yb.x = fmaxf((acc[p][2] - mb2.x) * mb2.y * gm.x + bt.x, 0.f);
                yb.y = fmaxf((acc[p][3] - mb2.x) * mb2.y * gm.y + bt.y, 0.f);
            } else yb = make_float2(0.f, 0.f);
            *(float2*)(oA + col) = ya;
            *(float2*)(oB + col) = yb;
        }
    }

    // ---- fused coords for this block's 64 rows ----
    if (tid < 64) {
        int i = row0 + tid;
        int b = i / Kq;
        int j = i - b * Kq;
        int off = 0;
        for (int t = 0; t < b; ++t) off += num_list[t];
        int valid = (j < min(num_list[b], Kq)) ? 1 : 0;
        int sidx  = max(0, min(off + j, M - 1));
        float x = 0.f, y = 0.f, z = 0.f;
        if (valid) {
            x = center[sidx * 3 + 0];
            y = center[sidx * 3 + 1];
            z = center[sidx * 3 + 2];
        }
        float c0 = (b < B - 1) ? (float)(b + 1) : 0.f;
        *(float4*)(out_coor + (size_t)i * 4) = make_float4(c0, x, y, z);
    }
}

extern "C" void kernel_launch(void* const* d_in, const int* in_sizes, int n_in,
                              void* d_out, int out_size) {
    const float* features = (const float*)d_in[0];
    const float* center   = (const float*)d_in[1];
    const void*  vidx     = d_in[2];
    const int*   num_list = (const int*)d_in[3];
    const float* Wm       = (const float*)d_in[4];
    const float* gamma    = (const float*)d_in[5];
    const float* beta     = (const float*)d_in[6];

    int C_OUT = in_sizes[5];                       // 128
    int M     = in_sizes[1] / 3;                   // 40000
    int K3    = in_sizes[2] / M;                   // 27
    int C_IN  = in_sizes[4] / (C_OUT * K3);        // 64
    int N     = in_sizes[0] / C_IN;                // 200000
    int B     = in_sizes[3];                       // 4
    int Kq    = out_size / (B * (C_OUT + 4));      // 2048
    int R     = B * Kq;                            // 8192

    float* out_feat = (float*)d_out;
    float* out_coor = out_feat + (size_t)R * C_OUT;

    // 2 launches/call: prep(0), main(1). ncu -s 5 -> main of the 2nd call.
    prep_w_kernel<<<(NK16 * 1024 + 255) / 256, 256>>>(Wm, vidx, in_sizes[2], N);

    dpc_mma_kernel<<<(R + 63) / 64, 256>>>(features, vidx, num_list, center,
                                           gamma, beta, out_feat, out_coor,
                                           N, M, K3, C_IN, B, Kq, R);
}